// round 3
// baseline (speedup 1.0000x reference)
#include <cuda_runtime.h>

// VectorQuantizer: N=262144 points (D=64), K=1024 codes.
// out = [ z_q (N*64 floats) | encoding_inds as float (N) ]
//
// Round 3: GEMM-style outer product. Block = 64 points x all 1024 codes.
// 256 threads = 16(tx point-groups) x 16(ty code-groups); each thread owns a
// 4x4 tile of fma2 accumulator chains. z-tile resident in SMEM; codebook
// streamed via double-buffered cp.async tiles of 64 codes. Exact reference
// rounding for the score: dist2 = fl( fl(zsq - 2*dot) + cb_sq ); argmin with
// first-index tie-break via packed (dist_bits,idx) u64 min (dist2 > 0 here).

#define DIMS    64
#define KCODES  1024
#define TPB     256
#define PTS_BLK 64
#define TILE_C  64
#define NTILES  (KCODES / TILE_C)

// SMEM float offsets
#define OFF_Z    0                  // 64*64      = 4096 floats
#define OFF_ZSQ  4096               // 64
#define OFF_CSQ  4160               // 1024
#define OFF_CB   5184               // 2 * 4096   = 8192 (16B aligned: 5184*4=20736)
#define SMEM_FLOATS (OFF_CB + 2 * TILE_C * DIMS)
#define SMEM_BYTES  (SMEM_FLOATS * 4)   // 53504 B

typedef unsigned long long u64;
typedef unsigned int u32;

__device__ float g_cbsq[KCODES];

static __device__ __forceinline__ void unpack2(u64 v, float& lo, float& hi) {
    u32 a, b;
    asm("mov.b64 {%0, %1}, %2;" : "=r"(a), "=r"(b) : "l"(v));
    lo = __uint_as_float(a);
    hi = __uint_as_float(b);
}
static __device__ __forceinline__ u64 fma2(u64 a, u64 b, u64 c) {
    u64 d;
    asm("fma.rn.f32x2 %0, %1, %2, %3;" : "=l"(d) : "l"(a), "l"(b), "l"(c));
    return d;
}

static __device__ __forceinline__ void cp_async16(u32 saddr, const void* gaddr) {
    asm volatile("cp.async.cg.shared.global [%0], [%1], 16;"
                 :: "r"(saddr), "l"(gaddr));
}
static __device__ __forceinline__ void cp_commit() {
    asm volatile("cp.async.commit_group;");
}
static __device__ __forceinline__ void cp_wait0() {
    asm volatile("cp.async.wait_group 0;" ::: "memory");
}

// ---------------------------------------------------------------------------
// cb_sq[k] = sequential fp32 sum of squares of codebook row k (matches ref).
__global__ void cbsq_kernel(const float* __restrict__ cb) {
    int k = blockIdx.x * blockDim.x + threadIdx.x;
    if (k < KCODES) {
        const float* r = cb + (size_t)k * DIMS;
        float s = 0.f;
#pragma unroll
        for (int i = 0; i < DIMS; i++)
            s = __fadd_rn(s, __fmul_rn(r[i], r[i]));
        g_cbsq[k] = s;
    }
}

// ---------------------------------------------------------------------------
__global__ __launch_bounds__(TPB, 2)
void vq_kernel(const float* __restrict__ z_e,
               const float* __restrict__ cb,
               float* __restrict__ out,
               int N) {
    extern __shared__ float smem[];
    float* s_z   = smem + OFF_Z;
    float* s_zsq = smem + OFF_ZSQ;
    float* s_csq = smem + OFF_CSQ;
    float* s_cb  = smem + OFF_CB;

    const int tid = threadIdx.x;
    const int tx  = tid & 15;   // point group
    const int ty  = tid >> 4;   // code group
    const int base = blockIdx.x * PTS_BLK;

    // --- prefetch codebook tile 0 into buffer 0 ---
    {
        u32 s0 = (u32)__cvta_generic_to_shared(s_cb) + tid * 16;
        const char* g0 = (const char*)cb + tid * 16;
#pragma unroll
        for (int i = 0; i < 4; i++)
            cp_async16(s0 + i * 4096, g0 + i * 4096);
        cp_commit();
    }

    // --- load z tile (64x64 floats) + csq, cooperative ---
    {
        const float4* zsrc = (const float4*)z_e;
        float4* zdst = (float4*)s_z;
        const int gf4_lim = (N * DIMS) / 4;
#pragma unroll
        for (int i = 0; i < 4; i++) {
            int e = tid + i * TPB;               // 0..1023
            int g = base * (DIMS / 4) + e;
            float4 v;
            if (g < gf4_lim) v = zsrc[g];
            else { v.x = v.y = v.z = v.w = 0.f; }
            zdst[e] = v;
        }
        ((float4*)s_csq)[tid] = ((const float4*)g_cbsq)[tid];
    }
    __syncthreads();

    // --- zsq per point (sequential fp32, matches reference path) ---
    if (tid < PTS_BLK) {
        const float* zr = s_z + tid * DIMS;
        float s = 0.f;
#pragma unroll
        for (int i = 0; i < DIMS; i++)
            s = __fadd_rn(s, __fmul_rn(zr[i], zr[i]));
        s_zsq[tid] = s;
    }
    __syncthreads();

    float zsqr[4];
#pragma unroll
    for (int p = 0; p < 4; p++) zsqr[p] = s_zsq[tx * 4 + p];

    float best[4] = {3.4e38f, 3.4e38f, 3.4e38f, 3.4e38f};
    int   bidx[4] = {0, 0, 0, 0};

    const float* zrow = s_z + (tx * 4) * DIMS;

    for (int t = 0; t < NTILES; ++t) {
        cp_wait0();
        __syncthreads();   // tile t visible to all threads

        // prefetch tile t+1 into the other buffer (nobody reads it now)
        if (t + 1 < NTILES) {
            float* nbuf = s_cb + ((t + 1) & 1) * (TILE_C * DIMS);
            u32 sdst = (u32)__cvta_generic_to_shared(nbuf) + tid * 16;
            const char* gsrc = (const char*)(cb + (size_t)(t + 1) * TILE_C * DIMS) + tid * 16;
#pragma unroll
            for (int i = 0; i < 4; i++)
                cp_async16(sdst + i * 4096, gsrc + i * 4096);
            cp_commit();
        }

        const float* crow = s_cb + (t & 1) * (TILE_C * DIMS) + (ty * 4) * DIMS;

        u64 acc[4][4];
#pragma unroll
        for (int p = 0; p < 4; p++)
#pragma unroll
            for (int c = 0; c < 4; c++) acc[p][c] = 0ull;

#pragma unroll 8
        for (int dp = 0; dp < DIMS / 2; ++dp) {
            u64 zv[4], cv[4];
#pragma unroll
            for (int p = 0; p < 4; p++)
                zv[p] = *(const u64*)(zrow + p * DIMS + dp * 2);
#pragma unroll
            for (int c = 0; c < 4; c++)
                cv[c] = *(const u64*)(crow + c * DIMS + dp * 2);
#pragma unroll
            for (int p = 0; p < 4; p++)
#pragma unroll
                for (int c = 0; c < 4; c++)
                    acc[p][c] = fma2(zv[p], cv[c], acc[p][c]);
        }

        // epilogue: 16 dists, exact reference rounding
#pragma unroll
        for (int c = 0; c < 4; c++) {
            const int code = t * TILE_C + ty * 4 + c;
            const float csq = s_csq[code];
#pragma unroll
            for (int p = 0; p < 4; p++) {
                float lo, hi;
                unpack2(acc[p][c], lo, hi);
                float dot = __fadd_rn(lo, hi);
                float d = __fadd_rn(__fmaf_rn(-2.f, dot, zsqr[p]), csq);
                if (d < best[p]) { best[p] = d; bidx[p] = code; }
            }
        }

        __syncthreads();   // all reads of buffer (t&1) done before reuse
    }

    // --- cross-ty argmin reduction: packed (dist_bits<<32)|idx, u64 min ---
    // dist2 ~ ||z||^2 > 0 always here, so float-bit ordering is monotone.
    u64* s_red = (u64*)(smem + OFF_CB);          // reuse cb buffers (16KB+)
#pragma unroll
    for (int p = 0; p < 4; p++)
        s_red[(tx * 4 + p) * 17 + ty] =
            (((u64)__float_as_uint(best[p])) << 32) | (u32)bidx[p];
    __syncthreads();

    int* s_idx = (int*)(smem + OFF_CSQ);         // reuse csq region
    if (tid < PTS_BLK) {
        u64 m = s_red[tid * 17];
#pragma unroll
        for (int j = 1; j < 16; j++) {
            u64 v = s_red[tid * 17 + j];
            if (v < m) m = v;
        }
        int idx = (int)(m & 0xffffffffu);
        s_idx[tid] = idx;
        if (base + tid < N)
            out[(size_t)N * DIMS + base + tid] = (float)idx;
    }
    __syncthreads();

    // --- gather z_q = codebook[idx] (bitwise exact) ---
    {
        const float4* cb4 = (const float4*)cb;
        float4* o4 = (float4*)out + (size_t)base * (DIMS / 4);
        for (int e = tid; e < PTS_BLK * (DIMS / 4); e += TPB) {
            int row = e >> 4;
            int q   = e & 15;
            if (base + row < N)
                o4[row * 16 + q] = cb4[(size_t)s_idx[row] * 16 + q];
        }
    }
}

// ---------------------------------------------------------------------------
extern "C" void kernel_launch(void* const* d_in, const int* in_sizes, int n_in,
                              void* d_out, int out_size) {
    const float* z_e = (const float*)d_in[0];
    const float* cb  = (const float*)d_in[1];
    float* out = (float*)d_out;
    const int N = in_sizes[0] / DIMS;

    cbsq_kernel<<<(KCODES + 255) / 256, 256>>>(cb);

    cudaFuncSetAttribute(vq_kernel, cudaFuncAttributeMaxDynamicSharedMemorySize,
                         SMEM_BYTES);
    const int grid = (N + PTS_BLK - 1) / PTS_BLK;
    vq_kernel<<<grid, TPB, SMEM_BYTES>>>(z_e, cb, out, N);
}

// round 4
// speedup vs baseline: 5.0770x; 5.0770x over previous
#include <cuda_runtime.h>

// VectorQuantizer: N=262144 points (D=64), K=1024 codes.
// out = [ z_q (N*64 floats) | encoding_inds as float (N) ]
//
// Round 4: 8x8 register tile per thread, conflict-free SMEM (row stride 66
// floats => lane banks 2*tx+2*dp cover all 32 banks once), interleaved
// point/code assignment (pt = tx + p*16, code = ty + c*16). Per dim-pair:
// 16 LDS.64 -> 64 fma2 (64 independent chains = ILP to hide all latency).
// Score keeps reference rounding exactly:
//   dist2 = fl( fl(zsq - 2*dot) + cb_sq ), argmin first-index tie-break.

#define DIMS    64
#define KCODES  1024
#define TPB     256
#define PTB     128               // points per block
#define TILE_C  128               // codes per smem tile
#define NTILES  (KCODES / TILE_C) // 8
#define ROWF    66                // padded row stride (floats), 66%32=2

// SMEM float offsets
#define OFF_Z    0                        // PTB*ROWF   = 8448
#define OFF_CB   (PTB * ROWF)             // TILE_C*ROWF= 8448
#define OFF_CSQ  (OFF_CB + TILE_C * ROWF) // 1024
#define OFF_ZSQ  (OFF_CSQ + KCODES)       // 128
#define SMEM_FLOATS (OFF_ZSQ + PTB)
#define SMEM_BYTES  (SMEM_FLOATS * 4)     // 72192 B

typedef unsigned long long u64;
typedef unsigned int u32;

__device__ float g_cbsq[KCODES];

static __device__ __forceinline__ void unpack2(u64 v, float& lo, float& hi) {
    u32 a, b;
    asm("mov.b64 {%0, %1}, %2;" : "=r"(a), "=r"(b) : "l"(v));
    lo = __uint_as_float(a);
    hi = __uint_as_float(b);
}
static __device__ __forceinline__ u64 fma2(u64 a, u64 b, u64 c) {
    u64 d;
    asm("fma.rn.f32x2 %0, %1, %2, %3;" : "=l"(d) : "l"(a), "l"(b), "l"(c));
    return d;
}

// ---------------------------------------------------------------------------
// cb_sq[k] = sequential fp32 sum of squares of codebook row k (matches ref).
__global__ void cbsq_kernel(const float* __restrict__ cb) {
    int k = blockIdx.x * blockDim.x + threadIdx.x;
    if (k < KCODES) {
        const float* r = cb + (size_t)k * DIMS;
        float s = 0.f;
#pragma unroll
        for (int i = 0; i < DIMS; i++)
            s = __fadd_rn(s, __fmul_rn(r[i], r[i]));
        g_cbsq[k] = s;
    }
}

// ---------------------------------------------------------------------------
__global__ __launch_bounds__(TPB, 1)
void vq_kernel(const float* __restrict__ z_e,
               const float* __restrict__ cb,
               float* __restrict__ out,
               int N) {
    extern __shared__ float smem[];
    float* s_z   = smem + OFF_Z;    // [PTB][ROWF]
    float* s_cb  = smem + OFF_CB;   // [TILE_C][ROWF]
    float* s_csq = smem + OFF_CSQ;  // [KCODES]
    float* s_zsq = smem + OFF_ZSQ;  // [PTB]

    const int tid = threadIdx.x;
    const int tx  = tid & 15;   // point lane: pts tx + p*16
    const int ty  = tid >> 4;   // code lane:  codes ty + c*16 (per tile)
    const int base = blockIdx.x * PTB;

    // --- stage z tile [PTB x DIMS] into padded rows; also csq ---
    {
        const float4* z4 = (const float4*)z_e;
        const int lim4 = (N * DIMS) / 4;
#pragma unroll
        for (int i = 0; i < 8; i++) {
            int e  = tid + i * TPB;      // 0..2047
            int pt = e >> 4;
            int q  = e & 15;
            float4 v;
            int g = (base + pt) * 16 + q;
            if (g < lim4) v = z4[g];
            else { v.x = v.y = v.z = v.w = 0.f; }
            float* dst = s_z + pt * ROWF + q * 4;
            *(float2*)(dst)     = make_float2(v.x, v.y);
            *(float2*)(dst + 2) = make_float2(v.z, v.w);
        }
#pragma unroll
        for (int i = 0; i < 4; i++)
            s_csq[tid + i * TPB] = g_cbsq[tid + i * TPB];
    }
    __syncthreads();

    // zsq per point (sequential fp32; argmin is invariant to zsq anyway)
    if (tid < PTB) {
        const float* zr = s_z + tid * ROWF;
        float s = 0.f;
#pragma unroll
        for (int i = 0; i < DIMS; i++)
            s = __fadd_rn(s, __fmul_rn(zr[i], zr[i]));
        s_zsq[tid] = s;
    }
    __syncthreads();

    float zsqr[8];
#pragma unroll
    for (int p = 0; p < 8; p++) zsqr[p] = s_zsq[tx + p * 16];

    float best[8];
    int   bidx[8];
#pragma unroll
    for (int p = 0; p < 8; p++) { best[p] = 3.4e38f; bidx[p] = 0; }

    const float* zbase = s_z + tx * ROWF;

    for (int t = 0; t < NTILES; ++t) {
        __syncthreads();   // previous tile fully consumed
        // stage codebook tile t (codes t*128 .. +128)
        {
            const float4* c4 = (const float4*)(cb + (size_t)t * TILE_C * DIMS);
#pragma unroll
            for (int i = 0; i < 8; i++) {
                int e  = tid + i * TPB;
                int kc = e >> 4;
                int q  = e & 15;
                float4 v = c4[e];
                float* dst = s_cb + kc * ROWF + q * 4;
                *(float2*)(dst)     = make_float2(v.x, v.y);
                *(float2*)(dst + 2) = make_float2(v.z, v.w);
            }
        }
        __syncthreads();

        u64 acc[8][8];
#pragma unroll
        for (int p = 0; p < 8; p++)
#pragma unroll
            for (int c = 0; c < 8; c++) acc[p][c] = 0ull;

        const float* cbbase = s_cb + ty * ROWF;

#pragma unroll 4
        for (int dp = 0; dp < DIMS / 2; ++dp) {
            u64 zv[8], cv[8];
#pragma unroll
            for (int p = 0; p < 8; p++)
                zv[p] = *(const u64*)(zbase + p * (16 * ROWF) + dp * 2);
#pragma unroll
            for (int c = 0; c < 8; c++)
                cv[c] = *(const u64*)(cbbase + c * (16 * ROWF) + dp * 2);
#pragma unroll
            for (int p = 0; p < 8; p++)
#pragma unroll
                for (int c = 0; c < 8; c++)
                    acc[p][c] = fma2(zv[p], cv[c], acc[p][c]);
        }

        // epilogue: 64 dists, exact reference rounding
#pragma unroll
        for (int c = 0; c < 8; c++) {
            const int code = t * TILE_C + c * 16 + ty;
            const float csq = s_csq[code];
#pragma unroll
            for (int p = 0; p < 8; p++) {
                float lo, hi;
                unpack2(acc[p][c], lo, hi);
                float dot = __fadd_rn(lo, hi);
                float d = __fadd_rn(__fmaf_rn(-2.f, dot, zsqr[p]), csq);
                if (d < best[p]) { best[p] = d; bidx[p] = code; }
            }
        }
    }

    // --- cross-ty argmin: packed (dist_bits<<32)|idx u64 min (dist2 > 0) ---
    __syncthreads();
    u64* s_red = (u64*)s_cb;   // reuse cb tile region (needs 128*17*8 B < 33KB)
#pragma unroll
    for (int p = 0; p < 8; p++)
        s_red[(tx + p * 16) * 17 + ty] =
            (((u64)__float_as_uint(best[p])) << 32) | (u32)bidx[p];
    __syncthreads();

    int* s_idx = (int*)s_zsq;  // reuse zsq region (128 ints)
    if (tid < PTB) {
        u64 m = s_red[tid * 17];
#pragma unroll
        for (int j = 1; j < 16; j++) {
            u64 v = s_red[tid * 17 + j];
            if (v < m) m = v;
        }
        int idx = (int)(m & 0xffffffffu);
        s_idx[tid] = idx;
        if (base + tid < N)
            out[(size_t)N * DIMS + base + tid] = (float)idx;
    }
    __syncthreads();

    // --- gather z_q = codebook[idx] (bitwise exact) ---
    {
        const float4* cb4 = (const float4*)cb;
        float4* o4 = (float4*)out;
#pragma unroll
        for (int i = 0; i < 8; i++) {
            int e  = tid + i * TPB;
            int pt = e >> 4;
            int q  = e & 15;
            if (base + pt < N)
                o4[(size_t)(base + pt) * 16 + q] = cb4[(size_t)s_idx[pt] * 16 + q];
        }
    }
}

// ---------------------------------------------------------------------------
extern "C" void kernel_launch(void* const* d_in, const int* in_sizes, int n_in,
                              void* d_out, int out_size) {
    const float* z_e = (const float*)d_in[0];
    const float* cb  = (const float*)d_in[1];
    float* out = (float*)d_out;
    const int N = in_sizes[0] / DIMS;

    cbsq_kernel<<<(KCODES + 255) / 256, 256>>>(cb);

    cudaFuncSetAttribute(vq_kernel, cudaFuncAttributeMaxDynamicSharedMemorySize,
                         SMEM_BYTES);
    const int grid = (N + PTB - 1) / PTB;
    vq_kernel<<<grid, TPB, SMEM_BYTES>>>(z_e, cb, out, N);
}